// round 2
// baseline (speedup 1.0000x reference)
#include <cuda_runtime.h>
#include <math.h>

// YOLO loss: preds [16384,7,7,30] f32, labels same, scalar f32 out.
// N_CELLS = 16384*49 = 802816 cells of 30 floats each.
// Single fused kernel: 6272 blocks x 128 threads, 128 cells/block.
//  - float4 gmem->smem staging (960 float4 per array per block)
//  - per-cell loss, block tree-reduce -> g_partials[block]
//  - last-block-done: final block reduces 6272 partials in double (fixed
//    order -> deterministic), writes out, resets ticket counter.

#define SIDE 7
#define NBATCH 16384
#define CELLS_PER_BLOCK 128
#define NUM_BLOCKS 6272          // 802816 / 128 exactly
#define FLOATS_PER_CELL 30
#define CHUNK (CELLS_PER_BLOCK * FLOATS_PER_CELL)   // 3840 floats
#define CHUNK4 (CHUNK / 4)                          // 960 float4

__device__ float g_partials[NUM_BLOCKS];
__device__ unsigned int g_ticket = 0;

__global__ __launch_bounds__(CELLS_PER_BLOCK)
void yolo_fused_kernel(const float* __restrict__ preds,
                       const float* __restrict__ labels,
                       float* __restrict__ out)
{
    __shared__ float4 sp4[CHUNK4];
    __shared__ float4 sl4[CHUNK4];

    const int t = threadIdx.x;
    const long long base4 = (long long)blockIdx.x * CHUNK4;

    const float4* __restrict__ p4 = (const float4*)preds + base4;
    const float4* __restrict__ l4 = (const float4*)labels + base4;

    // Vectorized coalesced staging: warp moves 2KB contiguous per iteration.
    #pragma unroll
    for (int j = 0; j < 7; j++) {
        int i = t + j * CELLS_PER_BLOCK;
        sp4[i] = p4[i];
        sl4[i] = l4[i];
    }
    if (t < CHUNK4 - 7 * CELLS_PER_BLOCK) {          // tail: 64 float4
        int i = t + 7 * CELLS_PER_BLOCK;
        sp4[i] = p4[i];
        sl4[i] = l4[i];
    }
    __syncthreads();

    const float* p = (const float*)sp4 + t * FLOATS_PER_CELL;
    const float* l = (const float*)sl4 + t * FLOATS_PER_CELL;

    const float s = 1.0f / (float)SIDE;
    float cell = 0.0f;

    float conf = l[4];
    if (conf == 0.0f) {
        // noobj: 0.5 * sum over both boxes of (pc - lc)^2, lc == 0 here
        float d0 = p[4] - l[4];
        float d1 = p[9] - l[9];
        cell = 0.5f * (d0 * d0 + d1 * d1);
    } else {
        // label box 0 corners + area
        float l1x = l[0] * s - 0.5f * l[2];
        float l1y = l[1] * s - 0.5f * l[3];
        float l2x = l[0] * s + 0.5f * l[2];
        float l2y = l[1] * s + 0.5f * l[3];
        float la  = l[2] * l[3];

        float iou0, iou1;
        #pragma unroll
        for (int b = 0; b < 2; b++) {
            const float* pb = p + b * 5;
            float p1x = pb[0] * s - 0.5f * pb[2];
            float p1y = pb[1] * s - 0.5f * pb[3];
            float p2x = pb[0] * s + 0.5f * pb[2];
            float p2y = pb[1] * s + 0.5f * pb[3];
            float iw = fmaxf(fminf(p2x, l2x) - fmaxf(p1x, l1x), 0.0f);
            float ih = fmaxf(fminf(p2y, l2y) - fmaxf(p1y, l1y), 0.0f);
            float inter = iw * ih;
            float pa = pb[2] * pb[3];
            float v = inter / (pa + la - inter);
            if (b == 0) iou0 = v; else iou1 = v;
        }

        // jnp.argmax: first max wins -> idx=1 only on strict iou1 > iou0
        int idx = (iou1 > iou0) ? 1 : 0;
        float maxiou = fmaxf(iou0, iou1);

        const float* pr = p + idx * 5;
        const float* lr = l + idx * 5;

        float dresp = pr[4] - maxiou;
        float resp  = dresp * dresp;

        float nrc = p[(1 - idx) * 5 + 4];
        float nr  = nrc * nrc;

        float dx = pr[0] - lr[0];
        float dy = pr[1] - lr[1];
        float xy = dx * dx + dy * dy;

        float dw = sqrtf(pr[2]) - sqrtf(lr[2]);
        float dh = sqrtf(pr[3]) - sqrtf(lr[3]);
        float wh = dw * dw + dh * dh;

        float cls = 0.0f;
        #pragma unroll
        for (int k = 10; k < 30; k++) {
            float d = p[k] - l[k];
            cls += d * d;
        }

        cell = 5.0f * (xy + wh) + 2.0f * resp + nr + cls;
    }

    // Block reduction: warp shuffle tree then cross-warp via smem.
    float v = cell;
    #pragma unroll
    for (int off = 16; off > 0; off >>= 1)
        v += __shfl_down_sync(0xFFFFFFFFu, v, off);

    __shared__ float wsum[CELLS_PER_BLOCK / 32];
    int lane = t & 31;
    int wid  = t >> 5;
    if (lane == 0) wsum[wid] = v;
    __syncthreads();

    __shared__ bool is_last;
    if (t == 0) {
        float acc = 0.0f;
        #pragma unroll
        for (int w = 0; w < CELLS_PER_BLOCK / 32; w++) acc += wsum[w];
        g_partials[blockIdx.x] = acc;
        __threadfence();
        unsigned int ticket = atomicAdd(&g_ticket, 1u);
        is_last = (ticket == NUM_BLOCKS - 1);
    }
    __syncthreads();

    // Last-arriving block performs the deterministic final reduction.
    if (is_last) {
        double acc = 0.0;
        #pragma unroll 1
        for (int i = t; i < NUM_BLOCKS; i += CELLS_PER_BLOCK)
            acc += (double)g_partials[i];

        #pragma unroll
        for (int off = 16; off > 0; off >>= 1)
            acc += __shfl_down_sync(0xFFFFFFFFu, acc, off);

        __shared__ double dsum[CELLS_PER_BLOCK / 32];
        if (lane == 0) dsum[wid] = acc;
        __syncthreads();

        if (t == 0) {
            double total = 0.0;
            #pragma unroll
            for (int w = 0; w < CELLS_PER_BLOCK / 32; w++) total += dsum[w];
            out[0] = (float)(total / (double)NBATCH);
            g_ticket = 0;   // reset for next launch / graph replay
        }
    }
}

extern "C" void kernel_launch(void* const* d_in, const int* in_sizes, int n_in,
                              void* d_out, int out_size)
{
    const float* preds  = (const float*)d_in[0];
    const float* labels = (const float*)d_in[1];
    float* out = (float*)d_out;

    yolo_fused_kernel<<<NUM_BLOCKS, CELLS_PER_BLOCK>>>(preds, labels, out);
}

// round 3
// speedup vs baseline: 1.1999x; 1.1999x over previous
#include <cuda_runtime.h>
#include <math.h>

// YOLO loss: preds [16384,7,7,30] f32, labels same, scalar f32 out.
// N_CHUNKS = 6272 chunks of 128 cells (30 floats each).
// Persistent fused kernel: 1036 blocks (148 SMs x 7 resident) x 128 threads.
//  - each block grid-strides over ~6 chunks, scalar coalesced smem staging
//    (the known-good R1 load path), per-thread register accumulator
//  - one block tree-reduce + one ticket atomic per block (1036 total)
//  - last-arriving block reduces 1036 partials in double, fixed order.

#define SIDE 7
#define NBATCH 16384
#define CELLS_PER_BLOCK 128
#define NUM_CHUNKS 6272          // 802816 / 128 exactly
#define PGRID 1036               // 148 * 7 persistent blocks
#define FLOATS_PER_CELL 30
#define CHUNK (CELLS_PER_BLOCK * FLOATS_PER_CELL)   // 3840 floats

__device__ float g_partials[PGRID];
__device__ unsigned int g_ticket = 0;

__global__ __launch_bounds__(CELLS_PER_BLOCK)
void yolo_persistent_kernel(const float* __restrict__ preds,
                            const float* __restrict__ labels,
                            float* __restrict__ out)
{
    __shared__ float sp[CHUNK];
    __shared__ float sl[CHUNK];

    const int t = threadIdx.x;
    const float s = 1.0f / (float)SIDE;
    float acc_cell = 0.0f;

    for (int c = blockIdx.x; c < NUM_CHUNKS; c += PGRID) {
        __syncthreads();   // protect smem from previous iteration's readers

        const long long base = (long long)c * CHUNK;

        // Scalar coalesced staging: warp moves 512B contiguous per iter.
        #pragma unroll
        for (int j = 0; j < FLOATS_PER_CELL; j++) {
            int i = t + j * CELLS_PER_BLOCK;
            sp[i] = preds[base + i];
            sl[i] = labels[base + i];
        }
        __syncthreads();

        const float* p = sp + t * FLOATS_PER_CELL;
        const float* l = sl + t * FLOATS_PER_CELL;

        float cell;
        float conf = l[4];
        if (conf == 0.0f) {
            // noobj: 0.5 * sum over both boxes of (pc - lc)^2, lc == 0 here
            float d0 = p[4] - l[4];
            float d1 = p[9] - l[9];
            cell = 0.5f * (d0 * d0 + d1 * d1);
        } else {
            // label box 0 corners + area
            float l1x = l[0] * s - 0.5f * l[2];
            float l1y = l[1] * s - 0.5f * l[3];
            float l2x = l[0] * s + 0.5f * l[2];
            float l2y = l[1] * s + 0.5f * l[3];
            float la  = l[2] * l[3];

            float iou0, iou1;
            #pragma unroll
            for (int b = 0; b < 2; b++) {
                const float* pb = p + b * 5;
                float p1x = pb[0] * s - 0.5f * pb[2];
                float p1y = pb[1] * s - 0.5f * pb[3];
                float p2x = pb[0] * s + 0.5f * pb[2];
                float p2y = pb[1] * s + 0.5f * pb[3];
                float iw = fmaxf(fminf(p2x, l2x) - fmaxf(p1x, l1x), 0.0f);
                float ih = fmaxf(fminf(p2y, l2y) - fmaxf(p1y, l1y), 0.0f);
                float inter = iw * ih;
                float pa = pb[2] * pb[3];
                float v = inter / (pa + la - inter);
                if (b == 0) iou0 = v; else iou1 = v;
            }

            // jnp.argmax: first max wins -> idx=1 only on strict iou1 > iou0
            int idx = (iou1 > iou0) ? 1 : 0;
            float maxiou = fmaxf(iou0, iou1);

            const float* pr = p + idx * 5;
            const float* lr = l + idx * 5;

            float dresp = pr[4] - maxiou;
            float resp  = dresp * dresp;

            float nrc = p[(1 - idx) * 5 + 4];
            float nr  = nrc * nrc;

            float dx = pr[0] - lr[0];
            float dy = pr[1] - lr[1];
            float xy = dx * dx + dy * dy;

            float dw = sqrtf(pr[2]) - sqrtf(lr[2]);
            float dh = sqrtf(pr[3]) - sqrtf(lr[3]);
            float wh = dw * dw + dh * dh;

            float cls = 0.0f;
            #pragma unroll
            for (int k = 10; k < 30; k++) {
                float d = p[k] - l[k];
                cls += d * d;
            }

            cell = 5.0f * (xy + wh) + 2.0f * resp + nr + cls;
        }

        acc_cell += cell;
    }

    // One block reduction at the end: warp shuffle tree then cross-warp.
    float v = acc_cell;
    #pragma unroll
    for (int off = 16; off > 0; off >>= 1)
        v += __shfl_down_sync(0xFFFFFFFFu, v, off);

    __shared__ float wsum[CELLS_PER_BLOCK / 32];
    int lane = t & 31;
    int wid  = t >> 5;
    if (lane == 0) wsum[wid] = v;
    __syncthreads();

    __shared__ bool is_last;
    if (t == 0) {
        float bacc = 0.0f;
        #pragma unroll
        for (int w = 0; w < CELLS_PER_BLOCK / 32; w++) bacc += wsum[w];
        g_partials[blockIdx.x] = bacc;
        __threadfence();
        unsigned int ticket = atomicAdd(&g_ticket, 1u);
        is_last = (ticket == PGRID - 1);
    }
    __syncthreads();

    // Last-arriving block: deterministic final reduction over 1036 partials.
    if (is_last) {
        double acc = 0.0;
        #pragma unroll 1
        for (int i = t; i < PGRID; i += CELLS_PER_BLOCK)
            acc += (double)g_partials[i];

        #pragma unroll
        for (int off = 16; off > 0; off >>= 1)
            acc += __shfl_down_sync(0xFFFFFFFFu, acc, off);

        __shared__ double dsum[CELLS_PER_BLOCK / 32];
        if (lane == 0) dsum[wid] = acc;
        __syncthreads();

        if (t == 0) {
            double total = 0.0;
            #pragma unroll
            for (int w = 0; w < CELLS_PER_BLOCK / 32; w++) total += dsum[w];
            out[0] = (float)(total / (double)NBATCH);
            g_ticket = 0;   // reset for next graph replay
        }
    }
}

extern "C" void kernel_launch(void* const* d_in, const int* in_sizes, int n_in,
                              void* d_out, int out_size)
{
    const float* preds  = (const float*)d_in[0];
    const float* labels = (const float*)d_in[1];
    float* out = (float*)d_out;

    yolo_persistent_kernel<<<PGRID, CELLS_PER_BLOCK>>>(preds, labels, out);
}

// round 4
// speedup vs baseline: 1.6661x; 1.3886x over previous
#include <cuda_runtime.h>
#include <cuda.h>
#include <math.h>
#include <stdint.h>

// YOLO loss: preds [16384,7,7,30] f32, labels same, scalar f32 out.
// Persistent fused kernel, cp.async double-buffered:
//   444 blocks (148 SM x 3) x 128 threads, 128 cells/chunk, 6272 chunks.
//   While computing chunk c from buffer A, chunk c+444 streams into buffer B
//   via cp.async.cg 16B copies (1 group in flight, wait_group 1).
//   Per-thread register accumulator; one block-reduce + one ticket atomic per
//   block; last-arriving block reduces 444 partials in double, fixed order.

#define SIDE 7
#define NBATCH 16384
#define CELLS_PER_BLOCK 128
#define NUM_CHUNKS 6272            // 802816 / 128 exactly
#define PGRID 444                  // 148 * 3 persistent blocks
#define FLOATS_PER_CELL 30
#define CHUNKF (CELLS_PER_BLOCK * FLOATS_PER_CELL)   // 3840 floats
#define CHUNK4 (CHUNKF / 4)                          // 960 float4 per array
#define BUF4 (2 * CHUNK4)                            // 1920 float4 per buffer
#define SMEM_BYTES (2 * BUF4 * 16)                   // 61440 B

__device__ float g_partials[PGRID];
__device__ unsigned int g_ticket = 0;

__device__ __forceinline__ void cp16(uint32_t smem_addr, const float4* gptr) {
    asm volatile("cp.async.cg.shared.global [%0], [%1], 16;\n"
                 :: "r"(smem_addr), "l"(gptr));
}

// Stage one chunk (960 float4 of preds + 960 of labels) into buffer `sbase`.
__device__ __forceinline__ void prefetch_chunk(uint32_t sbase,
                                               const float4* __restrict__ p4,
                                               const float4* __restrict__ l4,
                                               int chunk, int t)
{
    const long long b = (long long)chunk * CHUNK4;
    const float4* ps = p4 + b;
    const float4* ls = l4 + b;
    #pragma unroll
    for (int j = 0; j < 7; j++) {
        int i = t + j * CELLS_PER_BLOCK;
        cp16(sbase + (uint32_t)i * 16u, ps + i);
        cp16(sbase + (uint32_t)(CHUNK4 + i) * 16u, ls + i);
    }
    if (t < CHUNK4 - 7 * CELLS_PER_BLOCK) {   // tail: 64 float4 each
        int i = t + 7 * CELLS_PER_BLOCK;
        cp16(sbase + (uint32_t)i * 16u, ps + i);
        cp16(sbase + (uint32_t)(CHUNK4 + i) * 16u, ls + i);
    }
}

__device__ __forceinline__ float cell_loss(const float* __restrict__ p,
                                           const float* __restrict__ l)
{
    const float s = 1.0f / (float)SIDE;
    float conf = l[4];
    if (conf == 0.0f) {
        float d0 = p[4] - l[4];
        float d1 = p[9] - l[9];
        return 0.5f * (d0 * d0 + d1 * d1);
    }
    float l1x = l[0] * s - 0.5f * l[2];
    float l1y = l[1] * s - 0.5f * l[3];
    float l2x = l[0] * s + 0.5f * l[2];
    float l2y = l[1] * s + 0.5f * l[3];
    float la  = l[2] * l[3];

    float iou0, iou1;
    #pragma unroll
    for (int b = 0; b < 2; b++) {
        const float* pb = p + b * 5;
        float p1x = pb[0] * s - 0.5f * pb[2];
        float p1y = pb[1] * s - 0.5f * pb[3];
        float p2x = pb[0] * s + 0.5f * pb[2];
        float p2y = pb[1] * s + 0.5f * pb[3];
        float iw = fmaxf(fminf(p2x, l2x) - fmaxf(p1x, l1x), 0.0f);
        float ih = fmaxf(fminf(p2y, l2y) - fmaxf(p1y, l1y), 0.0f);
        float inter = iw * ih;
        float pa = pb[2] * pb[3];
        float v = inter / (pa + la - inter);
        if (b == 0) iou0 = v; else iou1 = v;
    }

    int idx = (iou1 > iou0) ? 1 : 0;   // jnp.argmax: first max wins
    float maxiou = fmaxf(iou0, iou1);

    const float* pr = p + idx * 5;
    const float* lr = l + idx * 5;

    float dresp = pr[4] - maxiou;
    float resp  = dresp * dresp;

    float nrc = p[(1 - idx) * 5 + 4];
    float nr  = nrc * nrc;

    float dx = pr[0] - lr[0];
    float dy = pr[1] - lr[1];
    float xy = dx * dx + dy * dy;

    float dw = sqrtf(pr[2]) - sqrtf(lr[2]);
    float dh = sqrtf(pr[3]) - sqrtf(lr[3]);
    float wh = dw * dw + dh * dh;

    float cls = 0.0f;
    #pragma unroll
    for (int k = 10; k < 30; k++) {
        float d = p[k] - l[k];
        cls += d * d;
    }

    return 5.0f * (xy + wh) + 2.0f * resp + nr + cls;
}

extern __shared__ float4 smem4[];   // [2][1920] float4: buf x (preds|labels)

__global__ __launch_bounds__(CELLS_PER_BLOCK)
void yolo_pipe_kernel(const float* __restrict__ preds,
                      const float* __restrict__ labels,
                      float* __restrict__ out)
{
    const int t = threadIdx.x;
    const float4* p4 = (const float4*)preds;
    const float4* l4 = (const float4*)labels;

    const uint32_t sbase = (uint32_t)__cvta_generic_to_shared(smem4);

    float acc_cell = 0.0f;

    int c = blockIdx.x;
    int buf = 0;

    // Prologue: prefetch first chunk into buffer 0.
    prefetch_chunk(sbase, p4, l4, c, t);
    asm volatile("cp.async.commit_group;\n" ::: "memory");

    while (c < NUM_CHUNKS) {
        int cn = c + PGRID;
        if (cn < NUM_CHUNKS)
            prefetch_chunk(sbase + (uint32_t)(buf ^ 1) * BUF4 * 16u, p4, l4, cn, t);
        asm volatile("cp.async.commit_group;\n" ::: "memory");

        // Wait until only the newest group may be outstanding -> current buf ready.
        asm volatile("cp.async.wait_group 1;\n" ::: "memory");
        __syncthreads();

        const float* sp = (const float*)(smem4 + buf * BUF4);
        const float* sl = sp + CHUNKF;
        acc_cell += cell_loss(sp + t * FLOATS_PER_CELL, sl + t * FLOATS_PER_CELL);

        __syncthreads();   // all reads done before this buffer is refilled
        buf ^= 1;
        c = cn;
    }

    // Block reduction: warp shuffle tree then cross-warp via smem.
    float v = acc_cell;
    #pragma unroll
    for (int off = 16; off > 0; off >>= 1)
        v += __shfl_down_sync(0xFFFFFFFFu, v, off);

    __shared__ float wsum[CELLS_PER_BLOCK / 32];
    int lane = t & 31;
    int wid  = t >> 5;
    if (lane == 0) wsum[wid] = v;
    __syncthreads();

    __shared__ bool is_last;
    if (t == 0) {
        float bacc = 0.0f;
        #pragma unroll
        for (int w = 0; w < CELLS_PER_BLOCK / 32; w++) bacc += wsum[w];
        g_partials[blockIdx.x] = bacc;
        __threadfence();
        unsigned int ticket = atomicAdd(&g_ticket, 1u);
        is_last = (ticket == PGRID - 1);
    }
    __syncthreads();

    // Last-arriving block: deterministic final reduction over 444 partials.
    if (is_last) {
        double acc = 0.0;
        #pragma unroll 1
        for (int i = t; i < PGRID; i += CELLS_PER_BLOCK)
            acc += (double)g_partials[i];

        #pragma unroll
        for (int off = 16; off > 0; off >>= 1)
            acc += __shfl_down_sync(0xFFFFFFFFu, acc, off);

        __shared__ double dsum[CELLS_PER_BLOCK / 32];
        if (lane == 0) dsum[wid] = acc;
        __syncthreads();

        if (t == 0) {
            double total = 0.0;
            #pragma unroll
            for (int w = 0; w < CELLS_PER_BLOCK / 32; w++) total += dsum[w];
            out[0] = (float)(total / (double)NBATCH);
            g_ticket = 0;   // reset for next graph replay
        }
    }
}

extern "C" void kernel_launch(void* const* d_in, const int* in_sizes, int n_in,
                              void* d_out, int out_size)
{
    const float* preds  = (const float*)d_in[0];
    const float* labels = (const float*)d_in[1];
    float* out = (float*)d_out;

    static bool attr_set = false;
    if (!attr_set) {
        cudaFuncSetAttribute(yolo_pipe_kernel,
                             cudaFuncAttributeMaxDynamicSharedMemorySize,
                             SMEM_BYTES);
        attr_set = true;
    }

    yolo_pipe_kernel<<<PGRID, CELLS_PER_BLOCK, SMEM_BYTES>>>(preds, labels, out);
}